// round 12
// baseline (speedup 1.0000x reference)
#include <cuda_runtime.h>
#include <cuda_fp16.h>

#define N_NODES 262144
#define N_EDGES 2097152
#define GRIDW 8
#define NCLUS 64
#define EPSBN 1e-5f

// ---------------- static device scratch ----------------
__device__ unsigned d_count[N_NODES];
__device__ unsigned d_offset[N_NODES];
__device__ unsigned d_cursor[N_NODES];
__device__ unsigned long long d_scanDesc[256];   // decoupled-lookback descriptors
__device__ int      d_sorted_src[N_EDGES + 8];
__device__ uint4    d_G1h[N_NODES * 2];   // fp16: G1 = x*W1_0 + b1 + pos*W1pos [N,16]
__device__ uint4    d_G2h[N_NODES * 4];   // fp16: G2 = W2a^T h1 + b2 + pos*W2pos [N,32]
__device__ unsigned char d_clus[N_NODES];
__device__ unsigned d_cnt64[NCLUS];
__device__ unsigned d_cur64[NCLUS];
__device__ int      d_perm[N_NODES];      // nodes binned by cluster
__device__ unsigned d_pool[NCLUS * 32];   // encoded nonneg-float max (0 = empty)
__device__ int      d_is64;

__device__ __forceinline__ unsigned warp_iscan(unsigned v, int lane) {
#pragma unroll
    for (int d = 1; d < 32; d <<= 1) {
        unsigned n = __shfl_up_sync(0xffffffffu, v, d);
        if (lane >= d) v += n;
    }
    return v;
}

__device__ __forceinline__ unsigned pack2(float a, float b) {
    __half2 h = __floats2half2_rn(a, b);
    return *reinterpret_cast<unsigned*>(&h);
}
__device__ __forceinline__ __half2 h2max(__half2 a, unsigned b) {
    return __hmax2(a, *reinterpret_cast<__half2*>(&b));
}

// ---------------- K0: zero scratch + detect edge dtype ------------------------
__global__ void __launch_bounds__(256) k_zero(const void* __restrict__ ei) {
    int t = blockIdx.x * blockDim.x + threadIdx.x;  // 1024 blocks: covers N
    d_count[t] = 0u;
    if (t < NCLUS * 32) d_pool[t] = 0u;
    if (t < NCLUS) d_cnt64[t] = 0u;
    if (t < 256) d_scanDesc[t] = 0ULL;
    if (t == 0) {
        const int* p = (const int*)ei;
        int all_hi_zero = 1;
#pragma unroll
        for (int k = 0; k < 64; k++)
            if (p[2 * k + 1] != 0) all_hi_zero = 0;
        d_is64 = all_hi_zero;
    }
}

// ---------------- K1: fused node init (G1, cluster, cluster-hist) + edge hist -
__global__ void __launch_bounds__(256) k_inithist(
    const float* __restrict__ x, const float* __restrict__ pos,
    const float* __restrict__ W1, const float* __restrict__ b1,
    const void* __restrict__ ei)
{
    __shared__ unsigned s_h[NCLUS];
    int t = threadIdx.x;
    if (t < NCLUS) s_h[t] = 0u;
    __syncthreads();

    int g = blockIdx.x * blockDim.x + t;   // grid = E/2 threads
    // ---- node part (first N threads) ----
    if (g < N_NODES) {
        int i = g;
        float xv = x[i];
        float px = pos[3 * i], py = pos[3 * i + 1], pz = pos[3 * i + 2];
        float gg[16];
#pragma unroll
        for (int c = 0; c < 16; c++) {
            float v = b1[c];
            v = fmaf(xv, W1[c],      v);
            v = fmaf(px, W1[16 + c], v);
            v = fmaf(py, W1[32 + c], v);
            v = fmaf(pz, W1[48 + c], v);
            gg[c] = v;
        }
        uint4 u0, u1;
        u0.x = pack2(gg[0],  gg[1]);  u0.y = pack2(gg[2],  gg[3]);
        u0.z = pack2(gg[4],  gg[5]);  u0.w = pack2(gg[6],  gg[7]);
        u1.x = pack2(gg[8],  gg[9]);  u1.y = pack2(gg[10], gg[11]);
        u1.z = pack2(gg[12], gg[13]); u1.w = pack2(gg[14], gg[15]);
        d_G1h[i * 2 + 0] = u0;
        d_G1h[i * 2 + 1] = u1;
        int gx = (int)floorf(px * 0.0625f);
        int gy = (int)floorf(py * 0.0625f);
        int cl = min(max(gx + gy * GRIDW, 0), NCLUS - 1);
        d_clus[i] = (unsigned char)cl;
        atomicAdd(&s_h[cl], 1u);
    }
    // ---- edge hist part (2 edges/thread) ----
    {
        int is64 = d_is64;
        int d0, d1;
        if (is64) {
            longlong2 v = ((const longlong2*)ei)[N_EDGES / 2 + g];
            d0 = (int)v.x; d1 = (int)v.y;
        } else {
            int2 v = ((const int2*)((const int*)ei + N_EDGES))[g];
            d0 = v.x; d1 = v.y;
        }
        d0 = min(max(d0, 0), N_NODES - 1);
        d1 = min(max(d1, 0), N_NODES - 1);
        atomicAdd(&d_count[d0], 1u);
        atomicAdd(&d_count[d1], 1u);
    }
    __syncthreads();
    if (t < NCLUS && s_h[t]) atomicAdd(&d_cnt64[t], s_h[t]);
}

// ---------------- K2: single-pass exclusive scan (decoupled lookback) ---------
__global__ void __launch_bounds__(1024) k_scan() {
    int t = threadIdx.x, b = blockIdx.x;
    int lane = t & 31, warp = t >> 5;
    int i = b * 1024 + t;
    unsigned v = d_count[i];
    unsigned incl = warp_iscan(v, lane);
    __shared__ unsigned sw[32];
    __shared__ unsigned s_prefix;
    if (lane == 31) sw[warp] = incl;
    __syncthreads();
    if (warp == 0) {
        unsigned w = sw[lane];
        unsigned wi = warp_iscan(w, lane);
        sw[lane] = wi - w;                 // exclusive warp offsets
        unsigned blockAgg = __shfl_sync(0xffffffffu, wi, 31);
        if (lane == 0) {
            if (b == 0) {
                atomicExch(&d_scanDesc[0], (2ULL << 32) | (unsigned long long)blockAgg);
                s_prefix = 0u;
            } else {
                atomicExch(&d_scanDesc[b], (1ULL << 32) | (unsigned long long)blockAgg);
                unsigned run = 0; int j = b - 1;
                while (true) {
                    unsigned long long dsc;
                    do { dsc = atomicAdd(&d_scanDesc[j], 0ULL); } while ((dsc >> 32) == 0ULL);
                    run += (unsigned)dsc;
                    if ((dsc >> 32) == 2ULL) break;
                    j--;
                }
                atomicExch(&d_scanDesc[b], (2ULL << 32) | (unsigned long long)(run + blockAgg));
                s_prefix = run;
            }
        }
    }
    __syncthreads();
    unsigned excl = incl - v + sw[warp] + s_prefix;
    d_offset[i] = excl;
    d_cursor[i] = excl;
    if (b == 0 && t == 0) {   // tiny 64-entry cluster scan (cnt64 ready since K1)
        unsigned run = 0;
#pragma unroll
        for (int c = 0; c < NCLUS; c++) { d_cur64[c] = run; run += d_cnt64[c]; }
    }
}

// ---------------- K3: scatter edges into CSR + 2-level node binning -----------
__global__ void __launch_bounds__(256) k_scatter(const void* __restrict__ ei) {
    __shared__ unsigned s_h[NCLUS];
    __shared__ unsigned s_base[NCLUS];
    int t = threadIdx.x;
    if (t < NCLUS) s_h[t] = 0u;
    __syncthreads();

    int g = blockIdx.x * blockDim.x + t;   // grid = E/2 threads
    // ---- edge scatter (2 edges/thread) ----
    {
        int is64 = d_is64;
        int s0, s1, dd0, dd1;
        if (is64) {
            longlong2 sv = ((const longlong2*)ei)[g];
            longlong2 dv = ((const longlong2*)ei)[N_EDGES / 2 + g];
            s0 = (int)sv.x; s1 = (int)sv.y; dd0 = (int)dv.x; dd1 = (int)dv.y;
        } else {
            int2 sv = ((const int2*)ei)[g];
            int2 dv = ((const int2*)((const int*)ei + N_EDGES))[g];
            s0 = sv.x; s1 = sv.y; dd0 = dv.x; dd1 = dv.y;
        }
        s0 = min(max(s0, 0), N_NODES - 1);
        s1 = min(max(s1, 0), N_NODES - 1);
        dd0 = min(max(dd0, 0), N_NODES - 1);
        dd1 = min(max(dd1, 0), N_NODES - 1);
        unsigned p0 = atomicAdd(&d_cursor[dd0], 1u);
        d_sorted_src[p0] = s0;
        unsigned p1 = atomicAdd(&d_cursor[dd1], 1u);
        d_sorted_src[p1] = s1;
    }
    // ---- node binning into perm (first N threads) ----
    bool has = g < N_NODES;
    int cl = 0; unsigned r = 0;
    if (has) {
        cl = d_clus[g];
        r = atomicAdd(&s_h[cl], 1u);
    }
    __syncthreads();
    if (t < NCLUS && s_h[t]) s_base[t] = atomicAdd(&d_cur64[t], s_h[t]);
    __syncthreads();
    if (has) d_perm[s_base[cl] + r] = g;
}

// ---------------- K4: layer1 pair-per-node seg-max(fp16), BN+ReLU, emit G2 ----
__global__ void __launch_bounds__(256) k_layer1(
    const float* __restrict__ pos,
    const float* __restrict__ W1,
    const float* __restrict__ bn1m, const float* __restrict__ bn1v,
    const float* __restrict__ bn1w, const float* __restrict__ bn1b,
    const float* __restrict__ W2,   const float* __restrict__ b2)
{
    __shared__ float s_w1p[48];
    __shared__ float s_a[16], s_b[16];
    __shared__ float s_W2a[16 * 32];
    __shared__ float s_W2p[96];
    __shared__ float s_b2[32];
    int t = threadIdx.x;
    if (t < 48) s_w1p[t] = W1[16 + t];
    if (t < 16) {
        float sc = bn1w[t] * rsqrtf(bn1v[t] + EPSBN);
        s_a[t] = sc;
        s_b[t] = bn1b[t] - bn1m[t] * sc;
    }
    for (int k = t; k < 512; k += 256) s_W2a[k] = W2[k];
    if (t < 96) s_W2p[t] = W2[16 * 32 + t];
    if (t < 32) s_b2[t] = b2[t];
    __syncthreads();

    int gid = blockIdx.x * blockDim.x + t;   // 2*N threads
    int i = gid >> 1, half = gid & 1;
    unsigned start = d_offset[i], deg = d_count[i];
    const __half2 NEGINF2 = __floats2half2_rn(-65504.0f, -65504.0f);
    __half2 acc0 = NEGINF2, acc1 = NEGINF2, acc2 = NEGINF2, acc3 = NEGINF2;

#pragma unroll 4
    for (unsigned e = 0; e < deg; e++) {
        int s = d_sorted_src[start + e];
        uint4 u = d_G1h[s * 2 + half];
        acc0 = h2max(acc0, u.x); acc1 = h2max(acc1, u.y);
        acc2 = h2max(acc2, u.z); acc3 = h2max(acc3, u.w);
    }
    float accf[8];
    {
        float2 f0 = __half22float2(acc0), f1 = __half22float2(acc1);
        float2 f2 = __half22float2(acc2), f3 = __half22float2(acc3);
        accf[0] = f0.x; accf[1] = f0.y; accf[2] = f1.x; accf[3] = f1.y;
        accf[4] = f2.x; accf[5] = f2.y; accf[6] = f3.x; accf[7] = f3.y;
    }

    float px = pos[3 * i], py = pos[3 * i + 1], pz = pos[3 * i + 2];
    int c0 = half * 8;
    float h[8];
#pragma unroll
    for (int j = 0; j < 8; j++) {
        int c = c0 + j;
        float dterm = px * s_w1p[c] + py * s_w1p[16 + c] + pz * s_w1p[32 + c];
        float agg = (deg == 0u) ? 0.0f : (accf[j] - dterm);
        h[j] = fmaxf(fmaf(agg, s_a[c], s_b[c]), 0.0f);
    }
    float oth[8];
#pragma unroll
    for (int j = 0; j < 8; j++) oth[j] = __shfl_xor_sync(0xffffffffu, h[j], 1);
    float hl[16];
#pragma unroll
    for (int j = 0; j < 8; j++) {
        hl[c0 + j] = h[j];
        hl[(c0 ^ 8) + j] = oth[j];
    }
    int cc0 = half * 16;
    float g2a[16];
#pragma unroll
    for (int k = 0; k < 16; k++) {
        int cc = cc0 + k;
        float v = s_b2[cc];
        v = fmaf(px, s_W2p[cc],      v);
        v = fmaf(py, s_W2p[32 + cc], v);
        v = fmaf(pz, s_W2p[64 + cc], v);
        g2a[k] = v;
    }
#pragma unroll
    for (int m = 0; m < 16; m++) {
        float hm = hl[m];
#pragma unroll
        for (int k = 0; k < 16; k++)
            g2a[k] = fmaf(hm, s_W2a[m * 32 + cc0 + k], g2a[k]);
    }
#pragma unroll
    for (int q = 0; q < 2; q++) {
        uint4 u;
        u.x = pack2(g2a[8 * q + 0], g2a[8 * q + 1]);
        u.y = pack2(g2a[8 * q + 2], g2a[8 * q + 3]);
        u.z = pack2(g2a[8 * q + 4], g2a[8 * q + 5]);
        u.w = pack2(g2a[8 * q + 6], g2a[8 * q + 7]);
        d_G2h[i * 4 + half * 2 + q] = u;
    }
}

// ---------------- K5: layer2 quad-per-node (perm order), warp-reduced pool ----
__global__ void __launch_bounds__(256) k_layer2pool(
    const float* __restrict__ pos,
    const float* __restrict__ W2,
    const float* __restrict__ bn2m, const float* __restrict__ bn2v,
    const float* __restrict__ bn2w, const float* __restrict__ bn2b)
{
    __shared__ float s_w2p[96];
    __shared__ float s_a[32], s_b[32];
    __shared__ unsigned s_pool[NCLUS * 32];
    int t = threadIdx.x;
    if (t < 96) s_w2p[t] = W2[16 * 32 + t];
    if (t < 32) {
        float sc = bn2w[t] * rsqrtf(bn2v[t] + EPSBN);
        s_a[t] = sc;
        s_b[t] = bn2b[t] - bn2m[t] * sc;
    }
#pragma unroll
    for (int q = 0; q < 8; q++) s_pool[q * 256 + t] = 0u;
    __syncthreads();

    int gid = blockIdx.x * blockDim.x + t;   // 4*N threads
    int slot = gid >> 2, q = gid & 3;
    int lane = t & 31;
    int i = d_perm[slot];
    unsigned start = d_offset[i], deg = d_count[i];
    const __half2 NEGINF2 = __floats2half2_rn(-65504.0f, -65504.0f);
    __half2 acc0 = NEGINF2, acc1 = NEGINF2, acc2 = NEGINF2, acc3 = NEGINF2;

#pragma unroll 4
    for (unsigned e = 0; e < deg; e++) {
        int s = d_sorted_src[start + e];
        uint4 u = d_G2h[s * 4 + q];
        acc0 = h2max(acc0, u.x); acc1 = h2max(acc1, u.y);
        acc2 = h2max(acc2, u.z); acc3 = h2max(acc3, u.w);
    }
    float accf[8];
    {
        float2 f0 = __half22float2(acc0), f1 = __half22float2(acc1);
        float2 f2 = __half22float2(acc2), f3 = __half22float2(acc3);
        accf[0] = f0.x; accf[1] = f0.y; accf[2] = f1.x; accf[3] = f1.y;
        accf[4] = f2.x; accf[5] = f2.y; accf[6] = f3.x; accf[7] = f3.y;
    }

    float px = pos[3 * i], py = pos[3 * i + 1], pz = pos[3 * i + 2];
    int cl = d_clus[i];
    int c0 = q * 8;
    float hv[8];
#pragma unroll
    for (int j = 0; j < 8; j++) {
        int c = c0 + j;
        float dterm = px * s_w2p[c] + py * s_w2p[32 + c] + pz * s_w2p[64 + c];
        float agg = (deg == 0u) ? 0.0f : (accf[j] - dterm);
        hv[j] = fmaxf(fmaf(agg, s_a[c], s_b[c]), 0.0f);   // >= 0
    }
    int cl0 = __shfl_sync(0xffffffffu, cl, 0);
    bool uni = __all_sync(0xffffffffu, cl == cl0);
    if (uni) {
        // reduce 8 nodes of the warp in registers (lanes with same q are 4 apart)
#pragma unroll
        for (int j = 0; j < 8; j++) {
            float v = hv[j];
            v = fmaxf(v, __shfl_xor_sync(0xffffffffu, v, 4));
            v = fmaxf(v, __shfl_xor_sync(0xffffffffu, v, 8));
            v = fmaxf(v, __shfl_xor_sync(0xffffffffu, v, 16));
            hv[j] = v;
        }
        if (lane < 4) {
            unsigned b = (unsigned)cl0 * 32u + (unsigned)lane * 8u;
#pragma unroll
            for (int j = 0; j < 8; j++)
                atomicMax(&s_pool[b + j], __float_as_uint(hv[j]) | 0x80000000u);
        }
    } else {
        unsigned b = (unsigned)cl * 32u + (unsigned)c0;
#pragma unroll
        for (int j = 0; j < 8; j++)
            atomicMax(&s_pool[b + j], __float_as_uint(hv[j]) | 0x80000000u);
    }
    __syncthreads();
#pragma unroll
    for (int qq = 0; qq < 8; qq++) {
        int j = qq * 256 + t;
        unsigned v = s_pool[j];
        if (v) atomicMax(&d_pool[j], v);
    }
}

// ---------------- K6: decode pooled -> output ---------------------------------
__global__ void k_out(float* __restrict__ out) {
    int t = blockIdx.x * blockDim.x + threadIdx.x;
    if (t < NCLUS * 32) {
        unsigned u = d_pool[t];
        out[t] = u ? __uint_as_float(u & 0x7FFFFFFFu) : 0.0f;
    }
}

// ---------------- host launch -------------------------------------------------
extern "C" void kernel_launch(void* const* d_in, const int* in_sizes, int n_in,
                              void* d_out, int out_size)
{
    const float* x    = (const float*)d_in[0];
    const float* pos  = (const float*)d_in[1];
    const void*  ei   = (const void*)d_in[2];
    const float* W1   = (const float*)d_in[3];
    const float* b1   = (const float*)d_in[4];
    const float* bn1m = (const float*)d_in[5];
    const float* bn1v = (const float*)d_in[6];
    const float* bn1w = (const float*)d_in[7];
    const float* bn1b = (const float*)d_in[8];
    const float* W2   = (const float*)d_in[9];
    const float* b2   = (const float*)d_in[10];
    const float* bn2m = (const float*)d_in[11];
    const float* bn2v = (const float*)d_in[12];
    const float* bn2w = (const float*)d_in[13];
    const float* bn2b = (const float*)d_in[14];
    float* out = (float*)d_out;

    k_zero<<<N_NODES / 256, 256>>>(ei);
    k_inithist<<<N_EDGES / 512, 256>>>(x, pos, W1, b1, ei);
    k_scan<<<256, 1024>>>();
    k_scatter<<<N_EDGES / 512, 256>>>(ei);
    k_layer1<<<N_NODES * 2 / 256, 256>>>(pos, W1, bn1m, bn1v, bn1w, bn1b, W2, b2);
    k_layer2pool<<<N_NODES * 4 / 256, 256>>>(pos, W2, bn2m, bn2v, bn2w, bn2b);
    k_out<<<8, 256>>>(out);
}

// round 14
// speedup vs baseline: 1.0217x; 1.0217x over previous
#include <cuda_runtime.h>
#include <cuda_fp16.h>

#define N_NODES 262144
#define N_EDGES 2097152
#define GRIDW 8
#define NCLUS 64
#define EPSBN 1e-5f

// ---------------- static device scratch ----------------
__device__ unsigned d_count[N_NODES];
__device__ unsigned d_excl[N_NODES];
__device__ unsigned d_offset[N_NODES];
__device__ unsigned d_cursor[N_NODES];
__device__ unsigned d_blockSum[256];
__device__ unsigned d_blockOff[256];
__device__ int      d_sorted_src[N_EDGES + 8];
__device__ uint4    d_G1h[N_NODES * 2];   // fp16: G1 = x*W1_0 + b1 + pos*W1pos [N,16]
__device__ uint4    d_G2h[N_NODES * 4];   // fp16: G2 = W2a^T h1 + b2 + pos*W2pos [N,32]
__device__ unsigned char d_clus[N_NODES];
__device__ unsigned d_pool[NCLUS * 32];   // encoded nonneg-float max (0 = empty)
__device__ int      d_is64;

__device__ __forceinline__ unsigned warp_iscan(unsigned v, int lane) {
#pragma unroll
    for (int d = 1; d < 32; d <<= 1) {
        unsigned n = __shfl_up_sync(0xffffffffu, v, d);
        if (lane >= d) v += n;
    }
    return v;
}

__device__ __forceinline__ unsigned pack2(float a, float b) {
    __half2 h = __floats2half2_rn(a, b);
    return *reinterpret_cast<unsigned*>(&h);
}
__device__ __forceinline__ __half2 h2max(__half2 a, unsigned b) {
    return __hmax2(a, *reinterpret_cast<__half2*>(&b));
}

// load 4 edge endpoints starting at element base+4*g (base in elements)
__device__ __forceinline__ void edge4(const void* ei, int is64, long long base4,
                                      int& a, int& b, int& c, int& d) {
    if (is64) {
        longlong2 v0 = ((const longlong2*)ei)[base4 >> 1];
        longlong2 v1 = ((const longlong2*)ei)[(base4 >> 1) + 1];
        a = (int)v0.x; b = (int)v0.y; c = (int)v1.x; d = (int)v1.y;
    } else {
        int4 v = ((const int4*)ei)[base4 >> 2];
        a = v.x; b = v.y; c = v.z; d = v.w;
    }
    a = min(max(a, 0), N_NODES - 1);
    b = min(max(b, 0), N_NODES - 1);
    c = min(max(c, 0), N_NODES - 1);
    d = min(max(d, 0), N_NODES - 1);
}

// ---------------- K0: zero scratch + detect edge dtype ------------------------
__global__ void __launch_bounds__(256) k_zero(const void* __restrict__ ei) {
    int t = blockIdx.x * blockDim.x + threadIdx.x;  // grid covers N
    d_count[t] = 0u;
    if (t < NCLUS * 32) d_pool[t] = 0u;
    if (t == 0) {
        const int* p = (const int*)ei;
        int all_hi_zero = 1;
#pragma unroll
        for (int k = 0; k < 64; k++)
            if (p[2 * k + 1] != 0) all_hi_zero = 0;
        d_is64 = all_hi_zero;
    }
}

// ---------------- K1: fused node init (G1, cluster) + edge hist (4/thread) ----
__global__ void __launch_bounds__(256) k_inithist(
    const float* __restrict__ x, const float* __restrict__ pos,
    const float* __restrict__ W1, const float* __restrict__ b1,
    const void* __restrict__ ei)
{
    int t = threadIdx.x;
    int g = blockIdx.x * blockDim.x + t;   // grid = E/4 threads (>= N)
    // ---- node part (first N threads) ----
    if (g < N_NODES) {
        int i = g;
        float xv = x[i];
        float px = pos[3 * i], py = pos[3 * i + 1], pz = pos[3 * i + 2];
        float gg[16];
#pragma unroll
        for (int c = 0; c < 16; c++) {
            float v = b1[c];
            v = fmaf(xv, W1[c],      v);
            v = fmaf(px, W1[16 + c], v);
            v = fmaf(py, W1[32 + c], v);
            v = fmaf(pz, W1[48 + c], v);
            gg[c] = v;
        }
        uint4 u0, u1;
        u0.x = pack2(gg[0],  gg[1]);  u0.y = pack2(gg[2],  gg[3]);
        u0.z = pack2(gg[4],  gg[5]);  u0.w = pack2(gg[6],  gg[7]);
        u1.x = pack2(gg[8],  gg[9]);  u1.y = pack2(gg[10], gg[11]);
        u1.z = pack2(gg[12], gg[13]); u1.w = pack2(gg[14], gg[15]);
        d_G1h[i * 2 + 0] = u0;
        d_G1h[i * 2 + 1] = u1;
        int gx = (int)floorf(px * 0.0625f);
        int gy = (int)floorf(py * 0.0625f);
        int cl = min(max(gx + gy * GRIDW, 0), NCLUS - 1);
        d_clus[i] = (unsigned char)cl;
    }
    // ---- edge hist (4 edges/thread, no-return atomics -> RED) ----
    {
        int is64 = d_is64;
        int d0, d1, d2, d3;
        edge4(ei, is64, (long long)N_EDGES + (long long)g * 4, d0, d1, d2, d3);
        atomicAdd(&d_count[d0], 1u);
        atomicAdd(&d_count[d1], 1u);
        atomicAdd(&d_count[d2], 1u);
        atomicAdd(&d_count[d3], 1u);
    }
}

// ---------------- K2/K3/K4: exclusive scan of d_count -------------------------
__global__ void __launch_bounds__(1024) k_scanA() {
    int t = threadIdx.x, b = blockIdx.x;
    int lane = t & 31, warp = t >> 5;
    int i = b * 1024 + t;
    unsigned v = d_count[i];
    unsigned incl = warp_iscan(v, lane);
    __shared__ unsigned sw[32];
    if (lane == 31) sw[warp] = incl;
    __syncthreads();
    if (warp == 0) {
        unsigned w = sw[lane];
        unsigned wi = warp_iscan(w, lane);
        sw[lane] = wi - w;
    }
    __syncthreads();
    unsigned excl = incl - v + sw[warp];
    d_excl[i] = excl;
    if (t == 1023) d_blockSum[b] = excl + v;
}

__global__ void k_scanB() {
    int t = threadIdx.x;  // 256 threads
    int lane = t & 31, warp = t >> 5;
    unsigned v = d_blockSum[t];
    unsigned incl = warp_iscan(v, lane);
    __shared__ unsigned sw[8];
    if (lane == 31) sw[warp] = incl;
    __syncthreads();
    if (warp == 0 && lane < 8) {
        unsigned w = sw[lane];
        unsigned wi = w;
#pragma unroll
        for (int d = 1; d < 8; d <<= 1) {
            unsigned n = __shfl_up_sync(0xffu, wi, d);
            if (lane >= d) wi += n;
        }
        sw[lane] = wi - w;
    }
    __syncthreads();
    d_blockOff[t] = incl - v + sw[warp];
}

__global__ void __launch_bounds__(1024) k_scanC() {
    int i = blockIdx.x * 1024 + threadIdx.x;
    unsigned o = d_excl[i] + d_blockOff[blockIdx.x];
    d_offset[i] = o;
    d_cursor[i] = o;
}

// ---------------- K5: scatter edges into CSR (4 edges/thread, phase-split) ----
__global__ void __launch_bounds__(256) k_scatter(const void* __restrict__ ei) {
    int g = blockIdx.x * blockDim.x + threadIdx.x;   // grid = E/4 threads
    int is64 = d_is64;
    int s0, s1, s2, s3, d0, d1, d2, d3;
    edge4(ei, is64, (long long)g * 4, s0, s1, s2, s3);
    edge4(ei, is64, (long long)N_EDGES + (long long)g * 4, d0, d1, d2, d3);
    // 4 independent atomic chains in flight
    unsigned p0 = atomicAdd(&d_cursor[d0], 1u);
    unsigned p1 = atomicAdd(&d_cursor[d1], 1u);
    unsigned p2 = atomicAdd(&d_cursor[d2], 1u);
    unsigned p3 = atomicAdd(&d_cursor[d3], 1u);
    d_sorted_src[p0] = s0;
    d_sorted_src[p1] = s1;
    d_sorted_src[p2] = s2;
    d_sorted_src[p3] = s3;
}

// ---------------- K6: layer1 pair-per-node seg-max(fp16), BN+ReLU, emit G2 ----
__global__ void __launch_bounds__(256) k_layer1(
    const float* __restrict__ pos,
    const float* __restrict__ W1,
    const float* __restrict__ bn1m, const float* __restrict__ bn1v,
    const float* __restrict__ bn1w, const float* __restrict__ bn1b,
    const float* __restrict__ W2,   const float* __restrict__ b2)
{
    __shared__ float s_w1p[48];
    __shared__ float s_a[16], s_b[16];
    __shared__ float s_W2a[16 * 32];
    __shared__ float s_W2p[96];
    __shared__ float s_b2[32];
    int t = threadIdx.x;
    if (t < 48) s_w1p[t] = W1[16 + t];
    if (t < 16) {
        float sc = bn1w[t] * rsqrtf(bn1v[t] + EPSBN);
        s_a[t] = sc;
        s_b[t] = bn1b[t] - bn1m[t] * sc;
    }
    for (int k = t; k < 512; k += 256) s_W2a[k] = W2[k];
    if (t < 96) s_W2p[t] = W2[16 * 32 + t];
    if (t < 32) s_b2[t] = b2[t];
    __syncthreads();

    int gid = blockIdx.x * blockDim.x + t;   // 2*N threads
    int i = gid >> 1, half = gid & 1;
    unsigned start = d_offset[i], deg = d_count[i];
    const __half2 NEGINF2 = __floats2half2_rn(-65504.0f, -65504.0f);
    __half2 acc0 = NEGINF2, acc1 = NEGINF2, acc2 = NEGINF2, acc3 = NEGINF2;

#pragma unroll 4
    for (unsigned e = 0; e < deg; e++) {
        int s = d_sorted_src[start + e];
        uint4 u = d_G1h[s * 2 + half];
        acc0 = h2max(acc0, u.x); acc1 = h2max(acc1, u.y);
        acc2 = h2max(acc2, u.z); acc3 = h2max(acc3, u.w);
    }
    float accf[8];
    {
        float2 f0 = __half22float2(acc0), f1 = __half22float2(acc1);
        float2 f2 = __half22float2(acc2), f3 = __half22float2(acc3);
        accf[0] = f0.x; accf[1] = f0.y; accf[2] = f1.x; accf[3] = f1.y;
        accf[4] = f2.x; accf[5] = f2.y; accf[6] = f3.x; accf[7] = f3.y;
    }

    float px = pos[3 * i], py = pos[3 * i + 1], pz = pos[3 * i + 2];
    int c0 = half * 8;
    float h[8];
#pragma unroll
    for (int j = 0; j < 8; j++) {
        int c = c0 + j;
        float dterm = px * s_w1p[c] + py * s_w1p[16 + c] + pz * s_w1p[32 + c];
        float agg = (deg == 0u) ? 0.0f : (accf[j] - dterm);
        h[j] = fmaxf(fmaf(agg, s_a[c], s_b[c]), 0.0f);
    }
    float oth[8];
#pragma unroll
    for (int j = 0; j < 8; j++) oth[j] = __shfl_xor_sync(0xffffffffu, h[j], 1);
    float hl[16];
#pragma unroll
    for (int j = 0; j < 8; j++) {
        hl[c0 + j] = h[j];
        hl[(c0 ^ 8) + j] = oth[j];
    }
    int cc0 = half * 16;
    float g2a[16];
#pragma unroll
    for (int k = 0; k < 16; k++) {
        int cc = cc0 + k;
        float v = s_b2[cc];
        v = fmaf(px, s_W2p[cc],      v);
        v = fmaf(py, s_W2p[32 + cc], v);
        v = fmaf(pz, s_W2p[64 + cc], v);
        g2a[k] = v;
    }
#pragma unroll
    for (int m = 0; m < 16; m++) {
        float hm = hl[m];
#pragma unroll
        for (int k = 0; k < 16; k++)
            g2a[k] = fmaf(hm, s_W2a[m * 32 + cc0 + k], g2a[k]);
    }
#pragma unroll
    for (int q = 0; q < 2; q++) {
        uint4 u;
        u.x = pack2(g2a[8 * q + 0], g2a[8 * q + 1]);
        u.y = pack2(g2a[8 * q + 2], g2a[8 * q + 3]);
        u.z = pack2(g2a[8 * q + 4], g2a[8 * q + 5]);
        u.w = pack2(g2a[8 * q + 6], g2a[8 * q + 7]);
        d_G2h[i * 4 + half * 2 + q] = u;
    }
}

// ---------------- K7: layer2 quad-per-node (natural order), shared pool -------
__global__ void __launch_bounds__(256) k_layer2pool(
    const float* __restrict__ pos,
    const float* __restrict__ W2,
    const float* __restrict__ bn2m, const float* __restrict__ bn2v,
    const float* __restrict__ bn2w, const float* __restrict__ bn2b)
{
    __shared__ float s_w2p[96];
    __shared__ float s_a[32], s_b[32];
    __shared__ unsigned s_pool[NCLUS * 32];
    int t = threadIdx.x;
    if (t < 96) s_w2p[t] = W2[16 * 32 + t];
    if (t < 32) {
        float sc = bn2w[t] * rsqrtf(bn2v[t] + EPSBN);
        s_a[t] = sc;
        s_b[t] = bn2b[t] - bn2m[t] * sc;
    }
#pragma unroll
    for (int q = 0; q < 8; q++) s_pool[q * 256 + t] = 0u;
    __syncthreads();

    int gid = blockIdx.x * blockDim.x + t;   // 4*N threads
    int i = gid >> 2, q = gid & 3;
    unsigned start = d_offset[i], deg = d_count[i];
    const __half2 NEGINF2 = __floats2half2_rn(-65504.0f, -65504.0f);
    __half2 acc0 = NEGINF2, acc1 = NEGINF2, acc2 = NEGINF2, acc3 = NEGINF2;

#pragma unroll 4
    for (unsigned e = 0; e < deg; e++) {
        int s = d_sorted_src[start + e];
        uint4 u = d_G2h[s * 4 + q];
        acc0 = h2max(acc0, u.x); acc1 = h2max(acc1, u.y);
        acc2 = h2max(acc2, u.z); acc3 = h2max(acc3, u.w);
    }
    float accf[8];
    {
        float2 f0 = __half22float2(acc0), f1 = __half22float2(acc1);
        float2 f2 = __half22float2(acc2), f3 = __half22float2(acc3);
        accf[0] = f0.x; accf[1] = f0.y; accf[2] = f1.x; accf[3] = f1.y;
        accf[4] = f2.x; accf[5] = f2.y; accf[6] = f3.x; accf[7] = f3.y;
    }

    float px = pos[3 * i], py = pos[3 * i + 1], pz = pos[3 * i + 2];
    unsigned base = (unsigned)d_clus[i] * 32u;
    int c0 = q * 8;
#pragma unroll
    for (int j = 0; j < 8; j++) {
        int c = c0 + j;
        float dterm = px * s_w2p[c] + py * s_w2p[32 + c] + pz * s_w2p[64 + c];
        float agg = (deg == 0u) ? 0.0f : (accf[j] - dterm);
        float h2v = fmaxf(fmaf(agg, s_a[c], s_b[c]), 0.0f);   // >= 0
        atomicMax(&s_pool[base + c], __float_as_uint(h2v) | 0x80000000u);
    }
    __syncthreads();
#pragma unroll
    for (int qq = 0; qq < 8; qq++) {
        int j = qq * 256 + t;
        unsigned v = s_pool[j];
        if (v) atomicMax(&d_pool[j], v);
    }
}

// ---------------- K8: decode pooled -> output ---------------------------------
__global__ void k_out(float* __restrict__ out) {
    int t = blockIdx.x * blockDim.x + threadIdx.x;
    if (t < NCLUS * 32) {
        unsigned u = d_pool[t];
        out[t] = u ? __uint_as_float(u & 0x7FFFFFFFu) : 0.0f;
    }
}

// ---------------- host launch -------------------------------------------------
extern "C" void kernel_launch(void* const* d_in, const int* in_sizes, int n_in,
                              void* d_out, int out_size)
{
    const float* x    = (const float*)d_in[0];
    const float* pos  = (const float*)d_in[1];
    const void*  ei   = (const void*)d_in[2];
    const float* W1   = (const float*)d_in[3];
    const float* b1   = (const float*)d_in[4];
    const float* bn1m = (const float*)d_in[5];
    const float* bn1v = (const float*)d_in[6];
    const float* bn1w = (const float*)d_in[7];
    const float* bn1b = (const float*)d_in[8];
    const float* W2   = (const float*)d_in[9];
    const float* b2   = (const float*)d_in[10];
    const float* bn2m = (const float*)d_in[11];
    const float* bn2v = (const float*)d_in[12];
    const float* bn2w = (const float*)d_in[13];
    const float* bn2b = (const float*)d_in[14];
    float* out = (float*)d_out;

    k_zero<<<N_NODES / 256, 256>>>(ei);
    k_inithist<<<N_EDGES / 1024, 256>>>(x, pos, W1, b1, ei);
    k_scanA<<<256, 1024>>>();
    k_scanB<<<1, 256>>>();
    k_scanC<<<256, 1024>>>();
    k_scatter<<<N_EDGES / 1024, 256>>>(ei);
    k_layer1<<<N_NODES * 2 / 256, 256>>>(pos, W1, bn1m, bn1v, bn1w, bn1b, W2, b2);
    k_layer2pool<<<N_NODES * 4 / 256, 256>>>(pos, W2, bn2m, bn2v, bn2w, bn2b);
    k_out<<<8, 256>>>(out);
}

// round 16
// speedup vs baseline: 1.0343x; 1.0123x over previous
#include <cuda_runtime.h>
#include <cuda_fp16.h>

#define N_NODES 262144
#define N_EDGES 2097152
#define GRIDW 8
#define NCLUS 64
#define EPSBN 1e-5f

// ---------------- static device scratch ----------------
__device__ unsigned d_count[N_NODES];
__device__ unsigned d_offset[N_NODES];
__device__ unsigned d_cursor[N_NODES];
__device__ unsigned long long d_scanDesc[256];   // decoupled-lookback descriptors
__device__ int      d_sorted_src[N_EDGES + 8];
__device__ uint4    d_G1h[N_NODES * 2];   // fp16: G1 = x*W1_0 + b1 + pos*W1pos [N,16]
__device__ uint4    d_G2h[N_NODES * 4];   // fp16: G2 = W2a^T h1 + b2 + pos*W2pos [N,32]
__device__ unsigned char d_clus[N_NODES];
__device__ unsigned d_pool[NCLUS * 32];   // encoded nonneg-float max (0 = empty)
__device__ unsigned d_done;               // last-block ticket for fused output
__device__ int      d_is64;

__device__ __forceinline__ unsigned warp_iscan(unsigned v, int lane) {
#pragma unroll
    for (int d = 1; d < 32; d <<= 1) {
        unsigned n = __shfl_up_sync(0xffffffffu, v, d);
        if (lane >= d) v += n;
    }
    return v;
}

__device__ __forceinline__ unsigned pack2(float a, float b) {
    __half2 h = __floats2half2_rn(a, b);
    return *reinterpret_cast<unsigned*>(&h);
}
__device__ __forceinline__ __half2 h2max(__half2 a, unsigned b) {
    return __hmax2(a, *reinterpret_cast<__half2*>(&b));
}

// load 4 edge endpoints starting at element base4 (element index, multiple of 4)
__device__ __forceinline__ void edge4(const void* ei, int is64, long long base4,
                                      int& a, int& b, int& c, int& d) {
    if (is64) {
        longlong2 v0 = ((const longlong2*)ei)[base4 >> 1];
        longlong2 v1 = ((const longlong2*)ei)[(base4 >> 1) + 1];
        a = (int)v0.x; b = (int)v0.y; c = (int)v1.x; d = (int)v1.y;
    } else {
        int4 v = ((const int4*)ei)[base4 >> 2];
        a = v.x; b = v.y; c = v.z; d = v.w;
    }
    a = min(max(a, 0), N_NODES - 1);
    b = min(max(b, 0), N_NODES - 1);
    c = min(max(c, 0), N_NODES - 1);
    d = min(max(d, 0), N_NODES - 1);
}

// ---------------- K0: zero scratch + detect edge dtype ------------------------
__global__ void __launch_bounds__(256) k_zero(const void* __restrict__ ei) {
    int t = blockIdx.x * blockDim.x + threadIdx.x;  // grid covers N
    d_count[t] = 0u;
    if (t < NCLUS * 32) d_pool[t] = 0u;
    if (t < 256) d_scanDesc[t] = 0ULL;
    if (t == 0) {
        d_done = 0u;
        const int* p = (const int*)ei;
        int all_hi_zero = 1;
#pragma unroll
        for (int k = 0; k < 64; k++)
            if (p[2 * k + 1] != 0) all_hi_zero = 0;
        d_is64 = all_hi_zero;
    }
}

// ---------------- K1: fused node init (G1, cluster) + edge hist (4/thread) ----
__global__ void __launch_bounds__(256) k_inithist(
    const float* __restrict__ x, const float* __restrict__ pos,
    const float* __restrict__ W1, const float* __restrict__ b1,
    const void* __restrict__ ei)
{
    int t = threadIdx.x;
    int g = blockIdx.x * blockDim.x + t;   // grid = E/4 threads (>= N/?)
    // ---- node part (first N threads) ----
    if (g < N_NODES) {
        int i = g;
        float xv = x[i];
        float px = pos[3 * i], py = pos[3 * i + 1], pz = pos[3 * i + 2];
        float gg[16];
#pragma unroll
        for (int c = 0; c < 16; c++) {
            float v = b1[c];
            v = fmaf(xv, W1[c],      v);
            v = fmaf(px, W1[16 + c], v);
            v = fmaf(py, W1[32 + c], v);
            v = fmaf(pz, W1[48 + c], v);
            gg[c] = v;
        }
        uint4 u0, u1;
        u0.x = pack2(gg[0],  gg[1]);  u0.y = pack2(gg[2],  gg[3]);
        u0.z = pack2(gg[4],  gg[5]);  u0.w = pack2(gg[6],  gg[7]);
        u1.x = pack2(gg[8],  gg[9]);  u1.y = pack2(gg[10], gg[11]);
        u1.z = pack2(gg[12], gg[13]); u1.w = pack2(gg[14], gg[15]);
        d_G1h[i * 2 + 0] = u0;
        d_G1h[i * 2 + 1] = u1;
        int gx = (int)floorf(px * 0.0625f);
        int gy = (int)floorf(py * 0.0625f);
        int cl = min(max(gx + gy * GRIDW, 0), NCLUS - 1);
        d_clus[i] = (unsigned char)cl;
    }
    // ---- edge hist (4 edges/thread, no-return atomics -> RED) ----
    {
        int is64 = d_is64;
        int d0, d1, d2, d3;
        edge4(ei, is64, (long long)N_EDGES + (long long)g * 4, d0, d1, d2, d3);
        atomicAdd(&d_count[d0], 1u);
        atomicAdd(&d_count[d1], 1u);
        atomicAdd(&d_count[d2], 1u);
        atomicAdd(&d_count[d3], 1u);
    }
}

// ---------------- K2: single-pass exclusive scan (decoupled lookback) ---------
__global__ void __launch_bounds__(1024) k_scan() {
    int t = threadIdx.x, b = blockIdx.x;
    int lane = t & 31, warp = t >> 5;
    int i = b * 1024 + t;
    unsigned v = d_count[i];
    unsigned incl = warp_iscan(v, lane);
    __shared__ unsigned sw[32];
    __shared__ unsigned s_prefix;
    if (lane == 31) sw[warp] = incl;
    __syncthreads();
    if (warp == 0) {
        unsigned w = sw[lane];
        unsigned wi = warp_iscan(w, lane);
        sw[lane] = wi - w;                 // exclusive warp offsets
        unsigned blockAgg = __shfl_sync(0xffffffffu, wi, 31);
        if (lane == 0) {
            if (b == 0) {
                atomicExch(&d_scanDesc[0], (2ULL << 32) | (unsigned long long)blockAgg);
                s_prefix = 0u;
            } else {
                atomicExch(&d_scanDesc[b], (1ULL << 32) | (unsigned long long)blockAgg);
                unsigned run = 0; int j = b - 1;
                while (true) {
                    unsigned long long dsc;
                    do { dsc = atomicAdd(&d_scanDesc[j], 0ULL); } while ((dsc >> 32) == 0ULL);
                    run += (unsigned)dsc;
                    if ((dsc >> 32) == 2ULL) break;
                    j--;
                }
                atomicExch(&d_scanDesc[b], (2ULL << 32) | (unsigned long long)(run + blockAgg));
                s_prefix = run;
            }
        }
    }
    __syncthreads();
    unsigned excl = incl - v + sw[warp] + s_prefix;
    d_offset[i] = excl;
    d_cursor[i] = excl;
}

// ---------------- K3: scatter edges into CSR (4 edges/thread) -----------------
__global__ void __launch_bounds__(256) k_scatter(const void* __restrict__ ei) {
    int g = blockIdx.x * blockDim.x + threadIdx.x;   // grid = E/4 threads
    int is64 = d_is64;
    int s0, s1, s2, s3, d0, d1, d2, d3;
    edge4(ei, is64, (long long)g * 4, s0, s1, s2, s3);
    edge4(ei, is64, (long long)N_EDGES + (long long)g * 4, d0, d1, d2, d3);
    unsigned p0 = atomicAdd(&d_cursor[d0], 1u);
    unsigned p1 = atomicAdd(&d_cursor[d1], 1u);
    unsigned p2 = atomicAdd(&d_cursor[d2], 1u);
    unsigned p3 = atomicAdd(&d_cursor[d3], 1u);
    d_sorted_src[p0] = s0;
    d_sorted_src[p1] = s1;
    d_sorted_src[p2] = s2;
    d_sorted_src[p3] = s3;
}

// ---------------- K4: layer1 pair-per-node seg-max(fp16), BN+ReLU, emit G2 ----
__global__ void __launch_bounds__(256) k_layer1(
    const float* __restrict__ pos,
    const float* __restrict__ W1,
    const float* __restrict__ bn1m, const float* __restrict__ bn1v,
    const float* __restrict__ bn1w, const float* __restrict__ bn1b,
    const float* __restrict__ W2,   const float* __restrict__ b2)
{
    __shared__ float s_w1p[48];
    __shared__ float s_a[16], s_b[16];
    __shared__ float s_W2a[16 * 32];
    __shared__ float s_W2p[96];
    __shared__ float s_b2[32];
    int t = threadIdx.x;
    if (t < 48) s_w1p[t] = W1[16 + t];
    if (t < 16) {
        float sc = bn1w[t] * rsqrtf(bn1v[t] + EPSBN);
        s_a[t] = sc;
        s_b[t] = bn1b[t] - bn1m[t] * sc;
    }
    for (int k = t; k < 512; k += 256) s_W2a[k] = W2[k];
    if (t < 96) s_W2p[t] = W2[16 * 32 + t];
    if (t < 32) s_b2[t] = b2[t];
    __syncthreads();

    int gid = blockIdx.x * blockDim.x + t;   // 2*N threads
    int i = gid >> 1, half = gid & 1;
    unsigned start = d_offset[i], deg = d_count[i];
    const __half2 NEGINF2 = __floats2half2_rn(-65504.0f, -65504.0f);
    __half2 acc0 = NEGINF2, acc1 = NEGINF2, acc2 = NEGINF2, acc3 = NEGINF2;

#pragma unroll 4
    for (unsigned e = 0; e < deg; e++) {
        int s = d_sorted_src[start + e];
        uint4 u = d_G1h[s * 2 + half];
        acc0 = h2max(acc0, u.x); acc1 = h2max(acc1, u.y);
        acc2 = h2max(acc2, u.z); acc3 = h2max(acc3, u.w);
    }
    float accf[8];
    {
        float2 f0 = __half22float2(acc0), f1 = __half22float2(acc1);
        float2 f2 = __half22float2(acc2), f3 = __half22float2(acc3);
        accf[0] = f0.x; accf[1] = f0.y; accf[2] = f1.x; accf[3] = f1.y;
        accf[4] = f2.x; accf[5] = f2.y; accf[6] = f3.x; accf[7] = f3.y;
    }

    float px = pos[3 * i], py = pos[3 * i + 1], pz = pos[3 * i + 2];
    int c0 = half * 8;
    float h[8];
#pragma unroll
    for (int j = 0; j < 8; j++) {
        int c = c0 + j;
        float dterm = px * s_w1p[c] + py * s_w1p[16 + c] + pz * s_w1p[32 + c];
        float agg = (deg == 0u) ? 0.0f : (accf[j] - dterm);
        h[j] = fmaxf(fmaf(agg, s_a[c], s_b[c]), 0.0f);
    }
    float oth[8];
#pragma unroll
    for (int j = 0; j < 8; j++) oth[j] = __shfl_xor_sync(0xffffffffu, h[j], 1);
    float hl[16];
#pragma unroll
    for (int j = 0; j < 8; j++) {
        hl[c0 + j] = h[j];
        hl[(c0 ^ 8) + j] = oth[j];
    }
    int cc0 = half * 16;
    float g2a[16];
#pragma unroll
    for (int k = 0; k < 16; k++) {
        int cc = cc0 + k;
        float v = s_b2[cc];
        v = fmaf(px, s_W2p[cc],      v);
        v = fmaf(py, s_W2p[32 + cc], v);
        v = fmaf(pz, s_W2p[64 + cc], v);
        g2a[k] = v;
    }
#pragma unroll
    for (int m = 0; m < 16; m++) {
        float hm = hl[m];
#pragma unroll
        for (int k = 0; k < 16; k++)
            g2a[k] = fmaf(hm, s_W2a[m * 32 + cc0 + k], g2a[k]);
    }
#pragma unroll
    for (int q = 0; q < 2; q++) {
        uint4 u;
        u.x = pack2(g2a[8 * q + 0], g2a[8 * q + 1]);
        u.y = pack2(g2a[8 * q + 2], g2a[8 * q + 3]);
        u.z = pack2(g2a[8 * q + 4], g2a[8 * q + 5]);
        u.w = pack2(g2a[8 * q + 6], g2a[8 * q + 7]);
        d_G2h[i * 4 + half * 2 + q] = u;
    }
}

// ---------------- K5: layer2 quad-per-node, shared pool, fused output ---------
__global__ void __launch_bounds__(1024) k_layer2pool(
    const float* __restrict__ pos,
    const float* __restrict__ W2,
    const float* __restrict__ bn2m, const float* __restrict__ bn2v,
    const float* __restrict__ bn2w, const float* __restrict__ bn2b,
    float* __restrict__ out)
{
    __shared__ float s_w2p[96];
    __shared__ float s_a[32], s_b[32];
    __shared__ unsigned s_pool[NCLUS * 32];
    __shared__ unsigned s_ticket;
    int t = threadIdx.x;
    if (t < 96) s_w2p[t] = W2[16 * 32 + t];
    if (t < 32) {
        float sc = bn2w[t] * rsqrtf(bn2v[t] + EPSBN);
        s_a[t] = sc;
        s_b[t] = bn2b[t] - bn2m[t] * sc;
    }
    s_pool[t] = 0u;
    s_pool[1024 + t] = 0u;
    __syncthreads();

    int gid = blockIdx.x * blockDim.x + t;   // 4*N threads, 1024/block
    int i = gid >> 2, q = gid & 3;
    unsigned start = d_offset[i], deg = d_count[i];
    const __half2 NEGINF2 = __floats2half2_rn(-65504.0f, -65504.0f);
    __half2 acc0 = NEGINF2, acc1 = NEGINF2, acc2 = NEGINF2, acc3 = NEGINF2;

#pragma unroll 4
    for (unsigned e = 0; e < deg; e++) {
        int s = d_sorted_src[start + e];
        uint4 u = d_G2h[s * 4 + q];
        acc0 = h2max(acc0, u.x); acc1 = h2max(acc1, u.y);
        acc2 = h2max(acc2, u.z); acc3 = h2max(acc3, u.w);
    }
    float accf[8];
    {
        float2 f0 = __half22float2(acc0), f1 = __half22float2(acc1);
        float2 f2 = __half22float2(acc2), f3 = __half22float2(acc3);
        accf[0] = f0.x; accf[1] = f0.y; accf[2] = f1.x; accf[3] = f1.y;
        accf[4] = f2.x; accf[5] = f2.y; accf[6] = f3.x; accf[7] = f3.y;
    }

    float px = pos[3 * i], py = pos[3 * i + 1], pz = pos[3 * i + 2];
    unsigned base = (unsigned)d_clus[i] * 32u;
    int c0 = q * 8;
#pragma unroll
    for (int j = 0; j < 8; j++) {
        int c = c0 + j;
        float dterm = px * s_w2p[c] + py * s_w2p[32 + c] + pz * s_w2p[64 + c];
        float agg = (deg == 0u) ? 0.0f : (accf[j] - dterm);
        float h2v = fmaxf(fmaf(agg, s_a[c], s_b[c]), 0.0f);   // >= 0
        atomicMax(&s_pool[base + c], __float_as_uint(h2v) | 0x80000000u);
    }
    __syncthreads();
    {
        unsigned v0 = s_pool[t];
        unsigned v1 = s_pool[1024 + t];
        if (v0) atomicMax(&d_pool[t], v0);
        if (v1) atomicMax(&d_pool[1024 + t], v1);
    }
    // ---- last-block decodes d_pool -> out (fused k_out) ----
    __threadfence();
    __syncthreads();
    if (t == 0) s_ticket = atomicAdd(&d_done, 1u);
    __syncthreads();
    if (s_ticket == gridDim.x - 1u) {
        unsigned u0 = d_pool[t];
        unsigned u1 = d_pool[1024 + t];
        out[t]        = u0 ? __uint_as_float(u0 & 0x7FFFFFFFu) : 0.0f;
        out[1024 + t] = u1 ? __uint_as_float(u1 & 0x7FFFFFFFu) : 0.0f;
    }
}

// ---------------- host launch -------------------------------------------------
extern "C" void kernel_launch(void* const* d_in, const int* in_sizes, int n_in,
                              void* d_out, int out_size)
{
    const float* x    = (const float*)d_in[0];
    const float* pos  = (const float*)d_in[1];
    const void*  ei   = (const void*)d_in[2];
    const float* W1   = (const float*)d_in[3];
    const float* b1   = (const float*)d_in[4];
    const float* bn1m = (const float*)d_in[5];
    const float* bn1v = (const float*)d_in[6];
    const float* bn1w = (const float*)d_in[7];
    const float* bn1b = (const float*)d_in[8];
    const float* W2   = (const float*)d_in[9];
    const float* b2   = (const float*)d_in[10];
    const float* bn2m = (const float*)d_in[11];
    const float* bn2v = (const float*)d_in[12];
    const float* bn2w = (const float*)d_in[13];
    const float* bn2b = (const float*)d_in[14];
    float* out = (float*)d_out;

    k_zero<<<N_NODES / 256, 256>>>(ei);
    k_inithist<<<N_EDGES / 1024, 256>>>(x, pos, W1, b1, ei);
    k_scan<<<256, 1024>>>();
    k_scatter<<<N_EDGES / 1024, 256>>>(ei);
    k_layer1<<<N_NODES * 2 / 256, 256>>>(pos, W1, bn1m, bn1v, bn1w, bn1b, W2, b2);
    k_layer2pool<<<N_NODES * 4 / 1024, 1024>>>(pos, W2, bn2m, bn2v, bn2w, bn2b, out);
}